// round 7
// baseline (speedup 1.0000x reference)
#include <cuda_runtime.h>
#include <math.h>
#include <stdint.h>

#define NNODES 64000
#define HDIM   256
#define NEDGE  1024000
#define LGNN   4
#define BATCH  16
#define SEQL   512
#define OUTD   256
#define H3     768
#define NROWS_OUT (BATCH*SEQL)   // 8192

// Select tcgen05 path only on arch-/family-specific device passes (sm_103a etc).
#if !defined(__CUDA_ARCH__) || defined(__CUDA_ARCH_FEAT_SM103_ALL) || \
    defined(__CUDA_ARCH_FEAT_SM100_ALL) || defined(__CUDA_ARCH_FEAT_SM101_ALL) || \
    defined(__CUDA_ARCH_SPECIFIC__) || defined(__CUDA_ARCH_FAMILY_SPECIFIC__)
#define TC_PATH 1
#else
#define TC_PATH 0
#endif

// ---------------- scratch (device globals; no allocation allowed) -----------
__device__ float g_h  [NNODES*HDIM];
__device__ float g_s  [NNODES*HDIM];
__device__ float g_rz [NNODES*512];       // sigmoid(r|z) gates
__device__ float g_wc [LGNN*H3*HDIM];
__device__ int   g_rowptr[NNODES+1];
__device__ int   g_fill  [NNODES];
__device__ int   g_srcs  [NEDGE];
__device__ float g_ws    [NEDGE];
__device__ int   g_ekey  [NEDGE];
__device__ int   g_bsum  [256];
__device__ float g_xcat  [NROWS_OUT*2*HDIM];

#if TC_PATH
// ================= tcgen05 helpers ==========================================
__device__ __forceinline__ uint32_t smem_u32(const void* p) {
    uint32_t a;
    asm("{ .reg .u64 t; cvta.to.shared.u64 t, %1; cvt.u32.u64 %0, t; }" : "=r"(a) : "l"(p));
    return a;
}
__device__ __forceinline__ uint32_t elect_one() {
    uint32_t pred;
    asm volatile("{\n\t.reg .pred p;\n\telect.sync _|p, 0xFFFFFFFF;\n\tselp.b32 %0, 1, 0, p;\n\t}" : "=r"(pred));
    return pred;
}
#define MBAR_INIT(a, c) asm volatile("mbarrier.init.shared.b64 [%0], %1;" :: "r"(a), "r"(c) : "memory")
#define MBAR_INVAL(a)   asm volatile("mbarrier.inval.shared.b64 [%0];" :: "r"(a) : "memory")
#define MBAR_WAIT(a, ph) do {                                                   \
    uint32_t _m = (a), _p = (ph), _d;                                           \
    asm volatile("{\n\t.reg .pred p;\n\t"                                       \
        "mbarrier.try_wait.parity.acquire.cta.shared::cta.b64 p, [%1], %2;\n\t" \
        "selp.b32 %0, 1, 0, p;\n\t}" : "=r"(_d) : "r"(_m), "r"(_p) : "memory"); \
    if (!_d) {                                                                  \
        asm volatile("{\n\t.reg .pred P1;\n\t"                                  \
            "W_%=:\n\t"                                                         \
            "mbarrier.try_wait.parity.acquire.cta.shared::cta.b64 P1, [%0], %1, 0x989680;\n\t" \
            "@P1 bra.uni D_%=;\n\t"                                             \
            "bra.uni W_%=;\n\t"                                                 \
            "D_%=:\n\t}" :: "r"(_m), "r"(_p) : "memory");                       \
    }                                                                           \
} while (0)
#define TC_ALLOC(sa, n)   asm volatile("tcgen05.alloc.cta_group::1.sync.aligned.shared::cta.b32 [%0], %1;" :: "r"(sa), "r"(n) : "memory")
#define TC_DEALLOC(t, n)  asm volatile("tcgen05.dealloc.cta_group::1.sync.aligned.b32 %0, %1;" :: "r"(t), "r"(n))
#define TC_RELINQ()       asm volatile("tcgen05.relinquish_alloc_permit.cta_group::1.sync.aligned;")
#define TC_COMMIT(mb)     asm volatile("tcgen05.commit.cta_group::1.mbarrier::arrive::one.shared::cluster.b64 [%0];" :: "r"(mb) : "memory")
#define TC_FENCE_AFTER()  asm volatile("tcgen05.fence::after_thread_sync;" ::: "memory")
#define TC_WAIT_LD()      asm volatile("tcgen05.wait::ld.sync.aligned;" ::: "memory")
#define FENCE_ASYNC()     asm volatile("fence.proxy.async.shared::cta;" ::: "memory")

#define TC_LD_X32(r, ta) \
    asm volatile("tcgen05.ld.sync.aligned.32x32b.x32.b32 " \
        "{%0, %1, %2, %3, %4, %5, %6, %7, %8, %9, %10, %11, %12, %13, %14, %15, " \
        " %16, %17, %18, %19, %20, %21, %22, %23, %24, %25, %26, %27, %28, %29, %30, %31}, [%32];" \
        : "=r"((r)[0]),  "=r"((r)[1]),  "=r"((r)[2]),  "=r"((r)[3]), \
          "=r"((r)[4]),  "=r"((r)[5]),  "=r"((r)[6]),  "=r"((r)[7]), \
          "=r"((r)[8]),  "=r"((r)[9]),  "=r"((r)[10]), "=r"((r)[11]), \
          "=r"((r)[12]), "=r"((r)[13]), "=r"((r)[14]), "=r"((r)[15]), \
          "=r"((r)[16]), "=r"((r)[17]), "=r"((r)[18]), "=r"((r)[19]), \
          "=r"((r)[20]), "=r"((r)[21]), "=r"((r)[22]), "=r"((r)[23]), \
          "=r"((r)[24]), "=r"((r)[25]), "=r"((r)[26]), "=r"((r)[27]), \
          "=r"((r)[28]), "=r"((r)[29]), "=r"((r)[30]), "=r"((r)[31]) \
        : "r"(ta))

static constexpr uint64_t DESC_BASE_SW128 =
    (uint64_t(2)  << 61) | (uint64_t(1) << 46) | (uint64_t(64) << 32) | (uint64_t(1) << 16);
__device__ __forceinline__ uint64_t make_desc(uint32_t addr) {
    return DESC_BASE_SW128 | ((uint64_t)(addr >> 4) & 0x3FFF);
}
__device__ __forceinline__ uint32_t tf32cvt(float f) {
    uint32_t r;
    asm("cvt.rna.tf32.f32 %0, %1;" : "=r"(r) : "f"(f));
    return r;
}
__device__ __forceinline__ void mma_tf32(uint32_t d_tmem, uint64_t a_desc, uint64_t b_desc,
                                         uint32_t idesc, uint32_t en) {
    asm volatile("{\n\t.reg .pred p;\n\tsetp.ne.u32 p, %4, 0;\n\t"
        "tcgen05.mma.cta_group::1.kind::tf32 [%0], %1, %2, %3, {%5, %5, %5, %5}, p;\n\t}"
        :: "r"(d_tmem), "l"(a_desc), "l"(b_desc), "r"(idesc), "r"(en), "r"(0u) : "memory");
}

// idesc: dtype F32(1<<4), atype/btype TF32, M=128 (8<<24); N selectable
static constexpr uint32_t IDESC_N128 = (8u << 24) | (16u << 17) | (2u << 10) | (2u << 7) | (1u << 4);
static constexpr uint32_t IDESC_N256 = (8u << 24) | (32u << 17) | (2u << 10) | (2u << 7) | (1u << 4);

// fill a tile of nRows x 32 floats (one SW128 atom column), K-stride 256, tf32-rounded
__device__ __forceinline__ void fill32(char* smem, int dst, const float* __restrict__ src,
                                       int rowBase, int nRows, int k0, int tid, int nthr) {
    for (int idx = tid; idx < nRows*8; idx += nthr) {
        int row = idx >> 3, c4 = (idx & 7) * 4;
        float4 v = *(const float4*)(src + (size_t)(rowBase + row)*256 + k0 + c4);
        uint4 t;
        t.x = tf32cvt(v.x); t.y = tf32cvt(v.y); t.z = tf32cvt(v.z); t.w = tf32cvt(v.w);
        int aoff = (row >> 3)*1024 + (row & 7)*128 + c4*4;
        aoff ^= ((aoff >> 3) & 0x70);
        *(uint4*)(smem + dst + aoff) = t;
    }
}

// chunk-64 tile loader used by k_gemm_tc (two atom columns)
__device__ __forceinline__ void load_tile_tf32(char* smem, int dstOff, const float* __restrict__ src,
                                               int rowBase, int K, int k0, int tid) {
    #pragma unroll
    for (int it = 0; it < 8; it++) {
        int idx = it*256 + tid;
        int row = idx >> 4;
        int col = (idx & 15) * 4;
        float4 v = *(const float4*)(src + (size_t)(rowBase + row)*K + k0 + col);
        uint4 t;
        t.x = tf32cvt(v.x); t.y = tf32cvt(v.y); t.z = tf32cvt(v.z); t.w = tf32cvt(v.w);
        int aoff = ((row >> 3) + (col >> 5)*16)*1024 + (row & 7)*128 + (col & 31)*4;
        aoff ^= ((aoff >> 3) & 0x70);
        *(uint4*)(smem + dstOff + aoff) = t;
    }
}
#endif  // TC_PATH helpers

// layer-kernel smem plan: [0] tmem ptr | [8] mbar | [16..1040) bias0 | [1040..2064) bias1
// buffers at 4096: each {A_s 16K | A_h 16K | B0 32K | B1 32K} = 96K, double buffered
#define LBUF0   4096
#define LBUFSZ  98304
#define SM_LAYER (4096 + 2*98304)      // 200704
#define TC_SMEM_BYTES (1024 + 2*65536) // k_gemm_tc plan (R6, unchanged)

// =================== k_rz: rz = sigmoid(s@Wc_rz + h@Whh_rz + b) ==============
// grid (2, 500), 512 threads. x selects gate half (0:r, 1:z).
__global__ void __launch_bounds__(512, 1) k_rz(const float* __restrict__ wcl,
                                               const float* __restrict__ whh,
                                               const float* __restrict__ bih,
                                               const float* __restrict__ bhh) {
#if TC_PATH
    extern __shared__ char smc[];
    uint32_t sb = smem_u32(smc);
    int tid = threadIdx.x;
    int wid = tid >> 5, lid = tid & 31;
    int xb = blockIdx.x;                  // 0 or 1
    int rowBase = blockIdx.y * 128;
    int unitBase = xb * 256;

    if (wid == 0) { TC_ALLOC(sb, 256); TC_RELINQ(); }
    if (tid == 0) MBAR_INIT(sb + 8, 1);
    if (tid < 256) *(float*)(smc + 16 + tid*4) = bih[unitBase + tid] + bhh[unitBase + tid];

    // prologue chunk 0
    fill32(smc, LBUF0 +     0, g_s, rowBase, 128, 0, tid, 512);
    fill32(smc, LBUF0 + 16384, g_h, rowBase, 128, 0, tid, 512);
    fill32(smc, LBUF0 + 32768, wcl, unitBase, 256, 0, tid, 512);
    fill32(smc, LBUF0 + 65536, whh, unitBase, 256, 0, tid, 512);
    __syncthreads();

    uint32_t tmem;
    asm volatile("ld.shared.b32 %0, [%1];" : "=r"(tmem) : "r"(sb));

    for (int c = 0; c < 8; c++) {
        int cur = c & 1;
        uint32_t base = sb + LBUF0 + cur*LBUFSZ;
        if (wid == 0) {
            FENCE_ASYNC();
            if (elect_one()) {
                #pragma unroll
                for (int srcI = 0; srcI < 2; srcI++) {
                    uint64_t ad = make_desc(base + srcI*16384);
                    uint64_t bd = make_desc(base + 32768 + srcI*32768);
                    #pragma unroll
                    for (int sub = 0; sub < 4; sub++) {
                        uint32_t en = !(c == 0 && srcI == 0 && sub == 0);
                        mma_tf32(tmem, ad + sub*2, bd + sub*2, IDESC_N256, en);
                    }
                }
                TC_COMMIT(sb + 8);
            }
        }
        if (c < 7) {
            int off = LBUF0 + (cur ^ 1)*LBUFSZ;
            int k0 = (c + 1)*32;
            fill32(smc, off +     0, g_s, rowBase, 128, k0, tid, 512);
            fill32(smc, off + 16384, g_h, rowBase, 128, k0, tid, 512);
            fill32(smc, off + 32768, wcl, unitBase, 256, k0, tid, 512);
            fill32(smc, off + 65536, whh, unitBase, 256, k0, tid, 512);
        }
        MBAR_WAIT(sb + 8, c & 1);
        __syncthreads();
    }

    // epilogue: sigmoid(D + bias) -> g_rz
    TC_FENCE_AFTER();
    float* stage = (float*)(smc + LBUF0);     // 128 x 33
    const float* bs = (const float*)(smc + 16);
    for (int g = 0; g < 8; g++) {
        if (wid < 4) {
            uint32_t d[32];
            TC_LD_X32(d, tmem + g*32);
            TC_WAIT_LD();
            int rl = wid*32 + lid;
            #pragma unroll
            for (int jj = 0; jj < 32; jj++) {
                float v = __uint_as_float(d[jj]) + bs[g*32 + jj];
                stage[rl*33 + jj] = 1.f / (1.f + expf(-v));
            }
        }
        __syncthreads();
        for (int i = tid; i < 4096; i += 512) {
            int r = i >> 5, cc = i & 31;
            g_rz[(size_t)(rowBase + r)*512 + unitBase + g*32 + cc] = stage[r*33 + cc];
        }
        __syncthreads();
    }

    if (tid == 0) MBAR_INVAL(sb + 8);
    __syncthreads();
    if (wid == 0) TC_DEALLOC(tmem, 256);
#else
    // fallback: dual-source tiled SGEMM + sigmoid. 512 thr as 16x32, 8x8/thread.
    extern __shared__ char smc[];
    float* As = (float*)(smc + 4096);     // [16][132]
    float* Ah = As + 16*132;
    float* Bs = Ah + 16*132;              // [16][264]
    float* Bh = Bs + 16*264;
    int tid = threadIdx.x;
    int ty = tid >> 5, tx = tid & 31;
    int xb = blockIdx.x;
    int rowBase = blockIdx.y * 128;
    int unitBase = xb * 256;

    float acc[8][8];
    #pragma unroll
    for (int i = 0; i < 8; i++)
        #pragma unroll
        for (int j = 0; j < 8; j++) acc[i][j] = 0.f;

    for (int k0 = 0; k0 < 256; k0 += 16) {
        {
            int f = tid, r = f >> 2, kc = (f & 3)*4;
            float4 va = *(const float4*)(g_s + (size_t)(rowBase + r)*256 + k0 + kc);
            As[(kc+0)*132 + r] = va.x; As[(kc+1)*132 + r] = va.y;
            As[(kc+2)*132 + r] = va.z; As[(kc+3)*132 + r] = va.w;
            float4 vh = *(const float4*)(g_h + (size_t)(rowBase + r)*256 + k0 + kc);
            Ah[(kc+0)*132 + r] = vh.x; Ah[(kc+1)*132 + r] = vh.y;
            Ah[(kc+2)*132 + r] = vh.z; Ah[(kc+3)*132 + r] = vh.w;
        }
        #pragma unroll
        for (int q = 0; q < 2; q++) {
            int f = q*512 + tid, r = f >> 2, kc = (f & 3)*4;
            float4 vb = *(const float4*)(wcl + (size_t)(unitBase + r)*256 + k0 + kc);
            Bs[(kc+0)*264 + r] = vb.x; Bs[(kc+1)*264 + r] = vb.y;
            Bs[(kc+2)*264 + r] = vb.z; Bs[(kc+3)*264 + r] = vb.w;
            float4 vc = *(const float4*)(whh + (size_t)(unitBase + r)*256 + k0 + kc);
            Bh[(kc+0)*264 + r] = vc.x; Bh[(kc+1)*264 + r] = vc.y;
            Bh[(kc+2)*264 + r] = vc.z; Bh[(kc+3)*264 + r] = vc.w;
        }
        __syncthreads();
        #pragma unroll
        for (int kk = 0; kk < 16; kk++) {
            float a1[8], a2[8], b1[8], b2[8];
            #pragma unroll
            for (int i = 0; i < 8; i++) { a1[i] = As[kk*132 + ty*8 + i]; a2[i] = Ah[kk*132 + ty*8 + i]; }
            #pragma unroll
            for (int j = 0; j < 8; j++) { b1[j] = Bs[kk*264 + tx*8 + j]; b2[j] = Bh[kk*264 + tx*8 + j]; }
            #pragma unroll
            for (int i = 0; i < 8; i++)
                #pragma unroll
                for (int j = 0; j < 8; j++) acc[i][j] += a1[i]*b1[j] + a2[i]*b2[j];
        }
        __syncthreads();
    }
    #pragma unroll
    for (int i = 0; i < 8; i++)
        #pragma unroll
        for (int j = 0; j < 8; j++) {
            int col = tx*8 + j;
            float v = acc[i][j] + bih[unitBase + col] + bhh[unitBase + col];
            g_rz[(size_t)(rowBase + ty*8 + i)*512 + unitBase + col] = 1.f / (1.f + expf(-v));
        }
#endif
}

// =================== k_nh: i_n, h_n in TMEM; fused GRU epilogue ==============
// grid (500), 512 threads.
__global__ void __launch_bounds__(512, 1) k_nh(const float* __restrict__ wcn,
                                               const float* __restrict__ whhn,
                                               const float* __restrict__ bihn,
                                               const float* __restrict__ bhhn) {
#if TC_PATH
    extern __shared__ char smc[];
    uint32_t sb = smem_u32(smc);
    int tid = threadIdx.x;
    int wid = tid >> 5, lid = tid & 31;
    int rowBase = blockIdx.x * 128;

    if (wid == 0) { TC_ALLOC(sb, 512); TC_RELINQ(); }
    if (tid == 0) MBAR_INIT(sb + 8, 1);
    if (tid < 256) {
        *(float*)(smc + 16   + tid*4) = bihn[tid];
        *(float*)(smc + 1040 + tid*4) = bhhn[tid];
    }

    fill32(smc, LBUF0 +     0, g_s,  rowBase, 128, 0, tid, 512);
    fill32(smc, LBUF0 + 16384, g_h,  rowBase, 128, 0, tid, 512);
    fill32(smc, LBUF0 + 32768, wcn,  0, 256, 0, tid, 512);
    fill32(smc, LBUF0 + 65536, whhn, 0, 256, 0, tid, 512);
    __syncthreads();

    uint32_t tmem;
    asm volatile("ld.shared.b32 %0, [%1];" : "=r"(tmem) : "r"(sb));

    for (int c = 0; c < 8; c++) {
        int cur = c & 1;
        uint32_t base = sb + LBUF0 + cur*LBUFSZ;
        if (wid == 0) {
            FENCE_ASYNC();
            if (elect_one()) {
                #pragma unroll
                for (int srcI = 0; srcI < 2; srcI++) {
                    uint64_t ad = make_desc(base + srcI*16384);
                    uint64_t bd = make_desc(base + 32768 + srcI*32768);
                    uint32_t dT = tmem + srcI*256;
                    #pragma unroll
                    for (int sub = 0; sub < 4; sub++) {
                        uint32_t en = !(c == 0 && sub == 0);
                        mma_tf32(dT, ad + sub*2, bd + sub*2, IDESC_N256, en);
                    }
                }
                TC_COMMIT(sb + 8);
            }
        }
        if (c < 7) {
            int off = LBUF0 + (cur ^ 1)*LBUFSZ;
            int k0 = (c + 1)*32;
            fill32(smc, off +     0, g_s,  rowBase, 128, k0, tid, 512);
            fill32(smc, off + 16384, g_h,  rowBase, 128, k0, tid, 512);
            fill32(smc, off + 32768, wcn,  0, 256, k0, tid, 512);
            fill32(smc, off + 65536, whhn, 0, 256, k0, tid, 512);
        }
        MBAR_WAIT(sb + 8, c & 1);
        __syncthreads();
    }

    // fused GRU epilogue
    TC_FENCE_AFTER();
    float* st_r = (float*)(smc + LBUF0);            // 128 x 33 each
    float* st_z = st_r + 128*33;
    float* st_h = st_z + 128*33;
    const float* bi = (const float*)(smc + 16);
    const float* bh = (const float*)(smc + 1040);
    for (int g = 0; g < 8; g++) {
        for (int i = tid; i < 4096; i += 512) {
            int r = i >> 5, cc = i & 31;
            size_t row = (size_t)(rowBase + r);
            st_r[r*33 + cc] = g_rz[row*512 +       g*32 + cc];
            st_z[r*33 + cc] = g_rz[row*512 + 256 + g*32 + cc];
            st_h[r*33 + cc] = g_h [row*256 +       g*32 + cc];
        }
        __syncthreads();
        if (wid < 4) {
            uint32_t di[32], dh[32];
            TC_LD_X32(di, tmem + g*32);
            TC_LD_X32(dh, tmem + 256 + g*32);
            TC_WAIT_LD();
            int rl = wid*32 + lid;
            #pragma unroll
            for (int jj = 0; jj < 32; jj++) {
                int j = g*32 + jj;
                float gin = __uint_as_float(di[jj]) + bi[j];
                float ghn = __uint_as_float(dh[jj]) + bh[j];
                float r_ = st_r[rl*33 + jj];
                float z_ = st_z[rl*33 + jj];
                float ho = st_h[rl*33 + jj];
                float nn = tanhf(gin + r_*ghn);
                st_h[rl*33 + jj] = (1.f - z_)*nn + z_*ho;
            }
        }
        __syncthreads();
        for (int i = tid; i < 4096; i += 512) {
            int r = i >> 5, cc = i & 31;
            g_h[(size_t)(rowBase + r)*256 + g*32 + cc] = st_h[r*33 + cc];
        }
        __syncthreads();
    }

    if (tid == 0) MBAR_INVAL(sb + 8);
    __syncthreads();
    if (wid == 0) TC_DEALLOC(tmem, 512);
#else
    // fallback: compute i_n and h_n tiles in registers, then GRU.
    extern __shared__ char smc[];
    float* As = (float*)(smc + 4096);
    float* Ah = As + 16*132;
    float* Bi = Ah + 16*132;              // [16][264]
    float* Bh2 = Bi + 16*264;
    int tid = threadIdx.x;
    int ty = tid >> 5, tx = tid & 31;
    int rowBase = blockIdx.x * 128;

    float ai[8][8], ah[8][8];
    #pragma unroll
    for (int i = 0; i < 8; i++)
        #pragma unroll
        for (int j = 0; j < 8; j++) { ai[i][j] = 0.f; ah[i][j] = 0.f; }

    for (int k0 = 0; k0 < 256; k0 += 16) {
        {
            int f = tid, r = f >> 2, kc = (f & 3)*4;
            float4 va = *(const float4*)(g_s + (size_t)(rowBase + r)*256 + k0 + kc);
            As[(kc+0)*132 + r] = va.x; As[(kc+1)*132 + r] = va.y;
            As[(kc+2)*132 + r] = va.z; As[(kc+3)*132 + r] = va.w;
            float4 vh = *(const float4*)(g_h + (size_t)(rowBase + r)*256 + k0 + kc);
            Ah[(kc+0)*132 + r] = vh.x; Ah[(kc+1)*132 + r] = vh.y;
            Ah[(kc+2)*132 + r] = vh.z; Ah[(kc+3)*132 + r] = vh.w;
        }
        #pragma unroll
        for (int q = 0; q < 2; q++) {
            int f = q*512 + tid, r = f >> 2, kc = (f & 3)*4;
            float4 vb = *(const float4*)(wcn + (size_t)r*256 + k0 + kc);
            Bi[(kc+0)*264 + r] = vb.x; Bi[(kc+1)*264 + r] = vb.y;
            Bi[(kc+2)*264 + r] = vb.z; Bi[(kc+3)*264 + r] = vb.w;
            float4 vc = *(const float4*)(whhn + (size_t)r*256 + k0 + kc);
            Bh2[(kc+0)*264 + r] = vc.x; Bh2[(kc+1)*264 + r] = vc.y;
            Bh2[(kc+2)*264 + r] = vc.z; Bh2[(kc+3)*264 + r] = vc.w;
        }
        __syncthreads();
        #pragma unroll
        for (int kk = 0; kk < 16; kk++) {
            float a1[8], a2[8], b1[8], b2[8];
            #pragma unroll
            for (int i = 0; i < 8; i++) { a1[i] = As[kk*132 + ty*8 + i]; a2[i] = Ah[kk*132 + ty*8 + i]; }
            #pragma unroll
            for (int j = 0; j < 8; j++) { b1[j] = Bi[kk*264 + tx*8 + j]; b2[j] = Bh2[kk*264 + tx*8 + j]; }
            #pragma unroll
            for (int i = 0; i < 8; i++)
                #pragma unroll
                for (int j = 0; j < 8; j++) { ai[i][j] += a1[i]*b1[j]; ah[i][j] += a2[i]*b2[j]; }
        }
        __syncthreads();
    }
    #pragma unroll
    for (int i = 0; i < 8; i++)
        #pragma unroll
        for (int j = 0; j < 8; j++) {
            int col = tx*8 + j;
            size_t row = (size_t)(rowBase + ty*8 + i);
            float gin = ai[i][j] + bihn[col];
            float ghn = ah[i][j] + bhhn[col];
            float r_ = g_rz[row*512 + col];
            float z_ = g_rz[row*512 + 256 + col];
            float ho = g_h[row*256 + col];
            g_h[row*256 + col] = (1.f - z_)*tanhf(gin + r_*ghn) + z_*ho;
        }
#endif
}

// =================== output-projection GEMM (R6, proven) =====================
__global__ void __launch_bounds__(256, 1) k_gemm_tc(const float* __restrict__ A,
                                                    const float* __restrict__ B,
                                                    const float* __restrict__ bias,
                                                    float* __restrict__ C, int K, int M) {
#if TC_PATH
    extern __shared__ char smc[];
    uint32_t sb = smem_u32(smc);
    int tid = threadIdx.x;
    int wid = tid >> 5, lid = tid & 31;
    int rowBase = blockIdx.y * 128;
    int colBase = blockIdx.x * 128;

    if (wid == 0) { TC_ALLOC(sb, 128); TC_RELINQ(); }
    if (tid == 0) MBAR_INIT(sb + 8, 1);
    if (tid < 128) *(float*)(smc + 16 + tid*4) = bias[colBase + tid];

    load_tile_tf32(smc, 1024,         A, rowBase, K, 0, tid);
    load_tile_tf32(smc, 1024 + 32768, B, colBase, K, 0, tid);
    __syncthreads();

    uint32_t tmem;
    asm volatile("ld.shared.b32 %0, [%1];" : "=r"(tmem) : "r"(sb));

    int nch = K / 64;
    for (int c = 0; c < nch; c++) {
        int cur = c & 1;
        uint32_t aA = sb + 1024 + cur*65536;
        uint32_t aB = aA + 32768;
        if (wid == 0) {
            FENCE_ASYNC();
            if (elect_one()) {
                uint64_t ad = make_desc(aA), bd = make_desc(aB);
                #pragma unroll
                for (int s = 0; s < 8; s++) {
                    uint64_t off = (uint64_t)(s >> 2)*1024 + (uint64_t)(s & 3)*2;
                    mma_tf32(tmem, ad + off, bd + off, IDESC_N128, (c | s) != 0);
                }
                TC_COMMIT(sb + 8);
            }
        }
        if (c + 1 < nch) {
            int nxt = cur ^ 1;
            load_tile_tf32(smc, 1024 + nxt*65536,         A, rowBase, K, (c+1)*64, tid);
            load_tile_tf32(smc, 1024 + nxt*65536 + 32768, B, colBase, K, (c+1)*64, tid);
        }
        MBAR_WAIT(sb + 8, c & 1);
        __syncthreads();
    }

    TC_FENCE_AFTER();
    float* stage = (float*)(smc + 1024);
    for (int g = 0; g < 4; g++) {
        if (wid < 4) {
            uint32_t d[32];
            TC_LD_X32(d, tmem + g*32);
            TC_WAIT_LD();
            int rl = wid*32 + lid;
            #pragma unroll
            for (int j = 0; j < 32; j++)
                stage[rl*36 + j] = __uint_as_float(d[j]) + *(float*)(smc + 16 + (g*32 + j)*4);
        }
        __syncthreads();
        #pragma unroll
        for (int it = 0; it < 4; it++) {
            int idx = it*256 + tid;
            int r = idx >> 3, c8 = idx & 7;
            float4 v = *(float4*)(stage + r*36 + c8*4);
            *(float4*)(C + (size_t)(rowBase + r)*M + colBase + g*32 + c8*4) = v;
        }
        __syncthreads();
    }

    if (tid == 0) MBAR_INVAL(sb + 8);
    __syncthreads();
    if (wid == 0) TC_DEALLOC(tmem, 128);
#else
    extern __shared__ char smc[];
    float* As = (float*)(smc + 1024);
    float* Bs = As + 16*132;
    int tid = threadIdx.x;
    int ty = tid >> 4, tx = tid & 15;
    int rowBase = blockIdx.y * 128;
    int colBase = blockIdx.x * 128;

    float acc[8][8];
    #pragma unroll
    for (int i = 0; i < 8; i++)
        #pragma unroll
        for (int j = 0; j < 8; j++) acc[i][j] = 0.f;

    for (int k0 = 0; k0 < K; k0 += 16) {
        #pragma unroll
        for (int q = 0; q < 2; q++) {
            int f = tid + q*256;
            int r = f >> 2, kc = (f & 3) * 4;
            float4 va = *(const float4*)(A + (size_t)(rowBase + r)*K + k0 + kc);
            As[(kc+0)*132 + r] = va.x; As[(kc+1)*132 + r] = va.y;
            As[(kc+2)*132 + r] = va.z; As[(kc+3)*132 + r] = va.w;
            float4 vb = *(const float4*)(B + (size_t)(colBase + r)*K + k0 + kc);
            Bs[(kc+0)*132 + r] = vb.x; Bs[(kc+1)*132 + r] = vb.y;
            Bs[(kc+2)*132 + r] = vb.z; Bs[(kc+3)*132 + r] = vb.w;
        }
        __syncthreads();
        #pragma unroll
        for (int kk = 0; kk < 16; kk++) {
            float a[8], b[8];
            #pragma unroll
            for (int i = 0; i < 8; i++) a[i] = As[kk*132 + ty*8 + i];
            #pragma unroll
            for (int j = 0; j < 8; j++) b[j] = Bs[kk*132 + tx*8 + j];
            #pragma unroll
            for (int i = 0; i < 8; i++)
                #pragma unroll
                for (int j = 0; j < 8; j++) acc[i][j] += a[i]*b[j];
        }
        __syncthreads();
    }
    #pragma unroll
    for (int i = 0; i < 8; i++) {
        #pragma unroll
        for (int j = 0; j < 8; j += 4) {
            float4 o;
            o.x = acc[i][j+0] + bias[colBase + tx*8 + j+0];
            o.y = acc[i][j+1] + bias[colBase + tx*8 + j+1];
            o.z = acc[i][j+2] + bias[colBase + tx*8 + j+2];
            o.w = acc[i][j+3] + bias[colBase + tx*8 + j+3];
            *(float4*)(C + (size_t)(rowBase + ty*8 + i)*M + colBase + tx*8 + j) = o;
        }
    }
#endif
}

// ---------------- CSR build --------------------------------------------------
__global__ void k_zero_fill() {
    int i = blockIdx.x*256 + threadIdx.x;
    if (i < NNODES) g_fill[i] = 0;
}
__global__ void k_count(const int* __restrict__ ei) {
    int e = blockIdx.x*256 + threadIdx.x;
    if (e < NEDGE) atomicAdd(&g_fill[ei[NEDGE + e]], 1);
}
__global__ void k_scanA() {
    __shared__ int sh[256];
    int t = threadIdx.x;
    int i = blockIdx.x*256 + t;
    int v = g_fill[i];
    sh[t] = v; __syncthreads();
    #pragma unroll
    for (int off = 1; off < 256; off <<= 1) {
        int x = (t >= off) ? sh[t-off] : 0;
        __syncthreads();
        sh[t] += x;
        __syncthreads();
    }
    g_rowptr[i] = sh[t] - v;
    if (t == 255) g_bsum[blockIdx.x] = sh[t];
}
__global__ void k_scanB() {
    __shared__ int sh[256];
    int t = threadIdx.x;
    int v = (t < 250) ? g_bsum[t] : 0;
    sh[t] = v; __syncthreads();
    #pragma unroll
    for (int off = 1; off < 256; off <<= 1) {
        int x = (t >= off) ? sh[t-off] : 0;
        __syncthreads();
        sh[t] += x;
        __syncthreads();
    }
    if (t < 250) g_bsum[t] = sh[t] - v;
}
__global__ void k_scanC() {
    int t = threadIdx.x;
    int i = blockIdx.x*256 + t;
    g_rowptr[i] += g_bsum[blockIdx.x];
    g_fill[i] = 0;
    if (i == 0) g_rowptr[NNODES] = NEDGE;
}
__global__ void k_scatter(const int* __restrict__ ei, const float* __restrict__ ew) {
    int e = blockIdx.x*256 + threadIdx.x;
    if (e >= NEDGE) return;
    int d = ei[NEDGE + e];
    int p = g_rowptr[d] + atomicAdd(&g_fill[d], 1);
    g_srcs[p] = ei[e];
    g_ws[p]   = ew[e];
    g_ekey[p] = e;
}
__global__ void k_sort() {
    int n = blockIdx.x*256 + threadIdx.x;
    if (n >= NNODES) return;
    int s0 = g_rowptr[n], s1 = g_rowptr[n+1];
    for (int i = s0 + 1; i < s1; i++) {
        int   k = g_ekey[i];
        int   s = g_srcs[i];
        float w = g_ws[i];
        int j = i - 1;
        while (j >= s0 && g_ekey[j] > k) {
            g_ekey[j+1] = g_ekey[j];
            g_srcs[j+1] = g_srcs[j];
            g_ws[j+1]   = g_ws[j];
            j--;
        }
        g_ekey[j+1] = k;
        g_srcs[j+1] = s;
        g_ws[j+1]   = w;
    }
}

// ---------------- combined weight WcT[l][m][j] = sum_d ggc[l][j][d]*wih[m][d] --
__global__ void k_wc(const float* __restrict__ ggc, const float* __restrict__ wih) {
    __shared__ float wrow[HDIM];
    int lm = blockIdx.x;
    int l = lm / H3, m = lm % H3;
    int j = threadIdx.x;
    wrow[j] = wih[m*HDIM + j];
    __syncthreads();
    const float* grow = ggc + (size_t)(l*HDIM + j) * HDIM;
    float acc = 0.f;
    #pragma unroll 8
    for (int d = 0; d < HDIM; d++) acc += grow[d]*wrow[d];
    g_wc[(size_t)lm*HDIM + j] = acc;
}

// ---------------- h0 = emb[x] -----------------------------------------------
__global__ void k_embed(const int* __restrict__ x, const float* __restrict__ emb) {
    int i4 = blockIdx.x*256 + threadIdx.x;
    int n = i4 >> 6, c = i4 & 63;
    int v = x[n];
    ((float4*)g_h)[i4] = ((const float4*)emb)[(size_t)v*64 + c];
}

// ---------------- s = A h (CSR weighted aggregation), warp per node ----------
__global__ void k_agg() {
    int warp = (blockIdx.x*blockDim.x + threadIdx.x) >> 5;
    int lane = threadIdx.x & 31;
    if (warp >= NNODES) return;
    int s0 = g_rowptr[warp], s1 = g_rowptr[warp+1];
    float4 a0 = make_float4(0.f,0.f,0.f,0.f);
    float4 a1 = a0;
    for (int e = s0; e < s1; e++) {
        int   sp = g_srcs[e];
        float w  = g_ws[e];
        const float4* r = ((const float4*)g_h) + (size_t)sp*64;
        float4 v0 = r[lane], v1 = r[lane+32];
        a0.x += w*v0.x; a0.y += w*v0.y; a0.z += w*v0.z; a0.w += w*v0.w;
        a1.x += w*v1.x; a1.y += w*v1.y; a1.z += w*v1.z; a1.w += w*v1.w;
    }
    float4* o = ((float4*)g_s) + (size_t)warp*64;
    o[lane] = a0; o[lane+32] = a1;
}

// ---------------- gather + concat for output GEMM ----------------------------
__global__ void k_gcat(const int* __restrict__ gidx, const float* __restrict__ enc) {
    int i4 = blockIdx.x*256 + threadIdx.x;
    int r = i4 >> 7, c = i4 & 127;
    float4 v;
    if (c < 64) {
        int node = gidx[r];
        v = ((const float4*)g_h)[(size_t)node*64 + c];
    } else {
        v = ((const float4*)enc)[(size_t)r*64 + (c - 64)];
    }
    ((float4*)g_xcat)[i4] = v;
}

// ---------------- launch -----------------------------------------------------
extern "C" void kernel_launch(void* const* d_in, const int* in_sizes, int n_in,
                              void* d_out, int out_size) {
    const int*   x    = (const int*)d_in[0];
    const int*   ei   = (const int*)d_in[1];
    const float* ew   = (const float*)d_in[2];
    const int*   gidx = (const int*)d_in[3];
    const float* enc  = (const float*)d_in[5];
    const float* emb  = (const float*)d_in[6];
    const float* ggc  = (const float*)d_in[7];
    const float* wih  = (const float*)d_in[8];
    const float* whh  = (const float*)d_in[9];
    const float* bih  = (const float*)d_in[10];
    const float* bhh  = (const float*)d_in[11];
    const float* outw = (const float*)d_in[12];
    const float* outb = (const float*)d_in[13];
    float*       out  = (float*)d_out;

    (void)in_sizes; (void)n_in; (void)out_size;

    float *wc_p, *xcat_p;
    cudaGetSymbolAddress((void**)&wc_p,   g_wc);
    cudaGetSymbolAddress((void**)&xcat_p, g_xcat);

    cudaFuncSetAttribute(k_rz,      cudaFuncAttributeMaxDynamicSharedMemorySize, SM_LAYER);
    cudaFuncSetAttribute(k_nh,      cudaFuncAttributeMaxDynamicSharedMemorySize, SM_LAYER);
    cudaFuncSetAttribute(k_gemm_tc, cudaFuncAttributeMaxDynamicSharedMemorySize, TC_SMEM_BYTES);

    // CSR build (deterministic via k_sort)
    k_zero_fill<<<250, 256>>>();
    k_count    <<<4000, 256>>>(ei);
    k_scanA    <<<250, 256>>>();
    k_scanB    <<<1, 256>>>();
    k_scanC    <<<250, 256>>>();
    k_scatter  <<<4000, 256>>>(ei, ew);
    k_sort     <<<250, 256>>>();

    k_wc    <<<LGNN*H3, 256>>>(ggc, wih);
    k_embed <<<16000, 256>>>(x, emb);

    for (int l = 0; l < LGNN; l++) {
        const float* wcl = wc_p + (size_t)l*H3*HDIM;
        k_agg<<<8000, 256>>>();
        k_rz<<<dim3(2, 500), 512, SM_LAYER>>>(wcl, whh, bih, bhh);
        k_nh<<<500, 512, SM_LAYER>>>(wcl + 512*HDIM, whh + 512*HDIM, bih + 512, bhh + 512);
    }

    k_gcat<<<4096, 256>>>(gidx, enc);
    dim3 g2(OUTD/128, NROWS_OUT/128);  // (2, 64)
    k_gemm_tc<<<g2, 256, TC_SMEM_BYTES>>>(xcat_p, outw, outb, out, 2*HDIM, OUTD);
}

// round 8
// speedup vs baseline: 1.3352x; 1.3352x over previous
#include <cuda_runtime.h>
#include <math.h>
#include <stdint.h>

#define NNODES 64000
#define HDIM   256
#define NEDGE  1024000
#define LGNN   4
#define BATCH  16
#define SEQL   512
#define OUTD   256
#define H3     768
#define NROWS_OUT (BATCH*SEQL)   // 8192

// Select tcgen05 path only on arch-/family-specific device passes (sm_103a etc).
#if !defined(__CUDA_ARCH__) || defined(__CUDA_ARCH_FEAT_SM103_ALL) || \
    defined(__CUDA_ARCH_FEAT_SM100_ALL) || defined(__CUDA_ARCH_FEAT_SM101_ALL) || \
    defined(__CUDA_ARCH_SPECIFIC__) || defined(__CUDA_ARCH_FAMILY_SPECIFIC__)
#define TC_PATH 1
#else
#define TC_PATH 0
#endif

// ---------------- scratch (device globals; no allocation allowed) -----------
__device__ float g_h  [NNODES*HDIM];
__device__ float g_s  [NNODES*HDIM];
__device__ float g_gi [NNODES*H3];
__device__ float g_gh [NNODES*H3];
__device__ float g_wc [LGNN*H3*HDIM];
__device__ int   g_rowptr[NNODES+1];
__device__ int   g_fill  [NNODES];
__device__ int   g_srcs  [NEDGE];
__device__ float g_ws    [NEDGE];
__device__ int   g_ekey  [NEDGE];
__device__ int   g_bsum  [256];
__device__ float g_xcat  [NROWS_OUT*2*HDIM];

#if TC_PATH
// ================= tcgen05 helpers ==========================================
__device__ __forceinline__ uint32_t smem_u32(const void* p) {
    uint32_t a;
    asm("{ .reg .u64 t; cvta.to.shared.u64 t, %1; cvt.u32.u64 %0, t; }" : "=r"(a) : "l"(p));
    return a;
}
__device__ __forceinline__ uint32_t elect_one() {
    uint32_t pred;
    asm volatile("{\n\t.reg .pred p;\n\telect.sync _|p, 0xFFFFFFFF;\n\tselp.b32 %0, 1, 0, p;\n\t}" : "=r"(pred));
    return pred;
}
#define MBAR_INIT(a, c) asm volatile("mbarrier.init.shared.b64 [%0], %1;" :: "r"(a), "r"(c) : "memory")
#define MBAR_INVAL(a)   asm volatile("mbarrier.inval.shared.b64 [%0];" :: "r"(a) : "memory")
#define MBAR_WAIT(a, ph) do {                                                   \
    uint32_t _m = (a), _p = (ph), _d;                                           \
    asm volatile("{\n\t.reg .pred p;\n\t"                                       \
        "mbarrier.try_wait.parity.acquire.cta.shared::cta.b64 p, [%1], %2;\n\t" \
        "selp.b32 %0, 1, 0, p;\n\t}" : "=r"(_d) : "r"(_m), "r"(_p) : "memory"); \
    if (!_d) {                                                                  \
        asm volatile("{\n\t.reg .pred P1;\n\t"                                  \
            "W_%=:\n\t"                                                         \
            "mbarrier.try_wait.parity.acquire.cta.shared::cta.b64 P1, [%0], %1, 0x989680;\n\t" \
            "@P1 bra.uni D_%=;\n\t"                                             \
            "bra.uni W_%=;\n\t"                                                 \
            "D_%=:\n\t}" :: "r"(_m), "r"(_p) : "memory");                       \
    }                                                                           \
} while (0)
#define TC_ALLOC(sa, n)   asm volatile("tcgen05.alloc.cta_group::1.sync.aligned.shared::cta.b32 [%0], %1;" :: "r"(sa), "r"(n) : "memory")
#define TC_DEALLOC(t, n)  asm volatile("tcgen05.dealloc.cta_group::1.sync.aligned.b32 %0, %1;" :: "r"(t), "r"(n))
#define TC_RELINQ()       asm volatile("tcgen05.relinquish_alloc_permit.cta_group::1.sync.aligned;")
#define TC_COMMIT(mb)     asm volatile("tcgen05.commit.cta_group::1.mbarrier::arrive::one.shared::cluster.b64 [%0];" :: "r"(mb) : "memory")
#define TC_FENCE_AFTER()  asm volatile("tcgen05.fence::after_thread_sync;" ::: "memory")
#define TC_WAIT_LD()      asm volatile("tcgen05.wait::ld.sync.aligned;" ::: "memory")
#define FENCE_ASYNC()     asm volatile("fence.proxy.async.shared::cta;" ::: "memory")

#define TC_LD_X32(r, ta) \
    asm volatile("tcgen05.ld.sync.aligned.32x32b.x32.b32 " \
        "{%0, %1, %2, %3, %4, %5, %6, %7, %8, %9, %10, %11, %12, %13, %14, %15, " \
        " %16, %17, %18, %19, %20, %21, %22, %23, %24, %25, %26, %27, %28, %29, %30, %31}, [%32];" \
        : "=r"((r)[0]),  "=r"((r)[1]),  "=r"((r)[2]),  "=r"((r)[3]), \
          "=r"((r)[4]),  "=r"((r)[5]),  "=r"((r)[6]),  "=r"((r)[7]), \
          "=r"((r)[8]),  "=r"((r)[9]),  "=r"((r)[10]), "=r"((r)[11]), \
          "=r"((r)[12]), "=r"((r)[13]), "=r"((r)[14]), "=r"((r)[15]), \
          "=r"((r)[16]), "=r"((r)[17]), "=r"((r)[18]), "=r"((r)[19]), \
          "=r"((r)[20]), "=r"((r)[21]), "=r"((r)[22]), "=r"((r)[23]), \
          "=r"((r)[24]), "=r"((r)[25]), "=r"((r)[26]), "=r"((r)[27]), \
          "=r"((r)[28]), "=r"((r)[29]), "=r"((r)[30]), "=r"((r)[31]) \
        : "r"(ta))

static constexpr uint64_t DESC_BASE_SW128 =
    (uint64_t(2)  << 61) | (uint64_t(1) << 46) | (uint64_t(64) << 32) | (uint64_t(1) << 16);
__device__ __forceinline__ uint64_t make_desc(uint32_t addr) {
    return DESC_BASE_SW128 | ((uint64_t)(addr >> 4) & 0x3FFF);
}
__device__ __forceinline__ uint32_t tf32cvt(float f) {
    uint32_t r;
    asm("cvt.rna.tf32.f32 %0, %1;" : "=r"(r) : "f"(f));
    return r;
}
__device__ __forceinline__ void mma_tf32(uint32_t d_tmem, uint64_t a_desc, uint64_t b_desc,
                                         uint32_t idesc, uint32_t en) {
    asm volatile("{\n\t.reg .pred p;\n\tsetp.ne.u32 p, %4, 0;\n\t"
        "tcgen05.mma.cta_group::1.kind::tf32 [%0], %1, %2, %3, {%5, %5, %5, %5}, p;\n\t}"
        :: "r"(d_tmem), "l"(a_desc), "l"(b_desc), "r"(idesc), "r"(en), "r"(0u) : "memory");
}

// idesc: dtype F32(1<<4), atype/btype TF32, M=128 (8<<24), N=256 (32<<17)
static constexpr uint32_t IDESC_N256 = (8u << 24) | (32u << 17) | (2u << 10) | (2u << 7) | (1u << 4);

// tile loader: nRows x 64 K-floats (two SW128 atom columns), tf32-rounded
__device__ __forceinline__ void load_tile64(char* smem, int dstOff, const float* __restrict__ src,
                                            int rowBase, int K, int k0, int tid, int nthr,
                                            int nRows, int atomsPerCol) {
    for (int idx = tid; idx < nRows*16; idx += nthr) {
        int row = idx >> 4;
        int col = (idx & 15) * 4;
        float4 v = *(const float4*)(src + (size_t)(rowBase + row)*K + k0 + col);
        uint4 t;
        t.x = tf32cvt(v.x); t.y = tf32cvt(v.y); t.z = tf32cvt(v.z); t.w = tf32cvt(v.w);
        int aoff = ((row >> 3) + (col >> 5)*atomsPerCol)*1024 + (row & 7)*128 + (col & 31)*4;
        aoff ^= ((aoff >> 3) & 0x70);
        *(uint4*)(smem + dstOff + aoff) = t;
    }
}
#endif  // TC_PATH helpers

// SMEM plan: [0] tmem ptr | [8] mbar | [16..1040) bias(256) | [2048..) buffers
// buffer: A(32KB) + B(64KB) = 96KB, double buffered -> 2048 + 196608 = 198656
#define GBUF0   2048
#define GBUFSZ  98304
#define TC_SMEM_BYTES (2048 + 2*98304)

// C[n, m] = sum_k A[n,k]*B[m,k] + bias[m]; block tile 128(n) x 256(m), 512 threads
__global__ void __launch_bounds__(512, 1) k_gemm_tc(const float* __restrict__ A,
                                                    const float* __restrict__ B,
                                                    const float* __restrict__ bias,
                                                    float* __restrict__ C, int K, int M) {
#if TC_PATH
    extern __shared__ char smc[];
    uint32_t sb = smem_u32(smc);
    int tid = threadIdx.x;
    int wid = tid >> 5, lid = tid & 31;
    int rowBase = blockIdx.y * 128;
    int colBase = blockIdx.x * 256;

    if (wid == 0) { TC_ALLOC(sb, 256); TC_RELINQ(); }
    if (tid == 0) MBAR_INIT(sb + 8, 1);
    if (tid < 256) *(float*)(smc + 16 + tid*4) = bias[colBase + tid];

    // prologue: chunk 0
    load_tile64(smc, GBUF0,         A, rowBase, K, 0, tid, 512, 128, 16);
    load_tile64(smc, GBUF0 + 32768, B, colBase, K, 0, tid, 512, 256, 32);
    __syncthreads();

    uint32_t tmem;
    asm volatile("ld.shared.b32 %0, [%1];" : "=r"(tmem) : "r"(sb));

    int nch = K / 64;
    for (int c = 0; c < nch; c++) {
        int cur = c & 1;
        uint32_t aA = sb + GBUF0 + cur*GBUFSZ;
        uint32_t aB = aA + 32768;
        if (wid == 0) {
            FENCE_ASYNC();
            if (elect_one()) {
                uint64_t ad = make_desc(aA), bd = make_desc(aB);
                #pragma unroll
                for (int s = 0; s < 8; s++) {
                    uint64_t aoff = (uint64_t)(s >> 2)*1024 + (uint64_t)(s & 3)*2;
                    uint64_t boff = (uint64_t)(s >> 2)*2048 + (uint64_t)(s & 3)*2;
                    mma_tf32(tmem, ad + aoff, bd + boff, IDESC_N256, (c | s) != 0);
                }
                TC_COMMIT(sb + 8);
            }
        }
        if (c + 1 < nch) {
            int nxt = cur ^ 1;
            load_tile64(smc, GBUF0 + nxt*GBUFSZ,         A, rowBase, K, (c+1)*64, tid, 512, 128, 16);
            load_tile64(smc, GBUF0 + nxt*GBUFSZ + 32768, B, colBase, K, (c+1)*64, tid, 512, 256, 32);
        }
        MBAR_WAIT(sb + 8, c & 1);
        __syncthreads();
    }

    // epilogue: TMEM -> staged SMEM -> coalesced global
    TC_FENCE_AFTER();
    float* stage = (float*)(smc + GBUF0);          // 128 rows x 36 floats
    const float* bs = (const float*)(smc + 16);
    for (int g = 0; g < 8; g++) {
        if (wid < 4) {
            uint32_t d[32];
            TC_LD_X32(d, tmem + g*32);
            TC_WAIT_LD();
            int rl = wid*32 + lid;
            #pragma unroll
            for (int j = 0; j < 32; j++)
                stage[rl*36 + j] = __uint_as_float(d[j]) + bs[g*32 + j];
        }
        __syncthreads();
        #pragma unroll
        for (int it = 0; it < 2; it++) {
            int idx = it*512 + tid;               // 1024 float4
            int r = idx >> 3, c8 = idx & 7;
            float4 v = *(float4*)(stage + r*36 + c8*4);
            *(float4*)(C + (size_t)(rowBase + r)*M + colBase + g*32 + c8*4) = v;
        }
        __syncthreads();
    }

    if (tid == 0) MBAR_INVAL(sb + 8);
    __syncthreads();
    if (wid == 0) TC_DEALLOC(tmem, 256);
#else
    // ---- fp32 fallback: 128x256 tile, 512 threads as 16x32, 8x8/thread ----
    extern __shared__ char smc[];
    float* As = (float*)(smc + 2048);             // [16][132]
    float* Bs = As + 16*132;                      // [16][264]
    int tid = threadIdx.x;
    int ty = tid >> 5, tx = tid & 31;
    int rowBase = blockIdx.y * 128;
    int colBase = blockIdx.x * 256;

    float acc[8][8];
    #pragma unroll
    for (int i = 0; i < 8; i++)
        #pragma unroll
        for (int j = 0; j < 8; j++) acc[i][j] = 0.f;

    for (int k0 = 0; k0 < K; k0 += 16) {
        {
            int f = tid, r = f >> 2, kc = (f & 3)*4;
            float4 va = *(const float4*)(A + (size_t)(rowBase + r)*K + k0 + kc);
            As[(kc+0)*132 + r] = va.x; As[(kc+1)*132 + r] = va.y;
            As[(kc+2)*132 + r] = va.z; As[(kc+3)*132 + r] = va.w;
        }
        #pragma unroll
        for (int q = 0; q < 2; q++) {
            int f = q*512 + tid, r = f >> 2, kc = (f & 3)*4;
            float4 vb = *(const float4*)(B + (size_t)(colBase + r)*K + k0 + kc);
            Bs[(kc+0)*264 + r] = vb.x; Bs[(kc+1)*264 + r] = vb.y;
            Bs[(kc+2)*264 + r] = vb.z; Bs[(kc+3)*264 + r] = vb.w;
        }
        __syncthreads();
        #pragma unroll
        for (int kk = 0; kk < 16; kk++) {
            float a[8], b[8];
            #pragma unroll
            for (int i = 0; i < 8; i++) a[i] = As[kk*132 + ty*8 + i];
            #pragma unroll
            for (int j = 0; j < 8; j++) b[j] = Bs[kk*264 + tx*8 + j];
            #pragma unroll
            for (int i = 0; i < 8; i++)
                #pragma unroll
                for (int j = 0; j < 8; j++) acc[i][j] += a[i]*b[j];
        }
        __syncthreads();
    }
    #pragma unroll
    for (int i = 0; i < 8; i++) {
        #pragma unroll
        for (int j = 0; j < 8; j += 4) {
            float4 o;
            o.x = acc[i][j+0] + bias[colBase + tx*8 + j+0];
            o.y = acc[i][j+1] + bias[colBase + tx*8 + j+1];
            o.z = acc[i][j+2] + bias[colBase + tx*8 + j+2];
            o.w = acc[i][j+3] + bias[colBase + tx*8 + j+3];
            *(float4*)(C + (size_t)(rowBase + ty*8 + i)*M + colBase + tx*8 + j) = o;
        }
    }
#endif
}

// ---------------- CSR build --------------------------------------------------
__global__ void k_zero_fill() {
    int i = blockIdx.x*256 + threadIdx.x;
    if (i < NNODES) g_fill[i] = 0;
}
__global__ void k_count(const int* __restrict__ ei) {
    int e = blockIdx.x*256 + threadIdx.x;
    if (e < NEDGE) atomicAdd(&g_fill[ei[NEDGE + e]], 1);
}
__global__ void k_scanA() {
    __shared__ int sh[256];
    int t = threadIdx.x;
    int i = blockIdx.x*256 + t;
    int v = g_fill[i];
    sh[t] = v; __syncthreads();
    #pragma unroll
    for (int off = 1; off < 256; off <<= 1) {
        int x = (t >= off) ? sh[t-off] : 0;
        __syncthreads();
        sh[t] += x;
        __syncthreads();
    }
    g_rowptr[i] = sh[t] - v;
    if (t == 255) g_bsum[blockIdx.x] = sh[t];
}
__global__ void k_scanB() {
    __shared__ int sh[256];
    int t = threadIdx.x;
    int v = (t < 250) ? g_bsum[t] : 0;
    sh[t] = v; __syncthreads();
    #pragma unroll
    for (int off = 1; off < 256; off <<= 1) {
        int x = (t >= off) ? sh[t-off] : 0;
        __syncthreads();
        sh[t] += x;
        __syncthreads();
    }
    if (t < 250) g_bsum[t] = sh[t] - v;
}
__global__ void k_scanC() {
    int t = threadIdx.x;
    int i = blockIdx.x*256 + t;
    g_rowptr[i] += g_bsum[blockIdx.x];
    g_fill[i] = 0;
    if (i == 0) g_rowptr[NNODES] = NEDGE;
}
__global__ void k_scatter(const int* __restrict__ ei, const float* __restrict__ ew) {
    int e = blockIdx.x*256 + threadIdx.x;
    if (e >= NEDGE) return;
    int d = ei[NEDGE + e];
    int p = g_rowptr[d] + atomicAdd(&g_fill[d], 1);
    g_srcs[p] = ei[e];
    g_ws[p]   = ew[e];
    g_ekey[p] = e;
}
__global__ void k_sort() {
    int n = blockIdx.x*256 + threadIdx.x;
    if (n >= NNODES) return;
    int s0 = g_rowptr[n], s1 = g_rowptr[n+1];
    for (int i = s0 + 1; i < s1; i++) {
        int   k = g_ekey[i];
        int   s = g_srcs[i];
        float w = g_ws[i];
        int j = i - 1;
        while (j >= s0 && g_ekey[j] > k) {
            g_ekey[j+1] = g_ekey[j];
            g_srcs[j+1] = g_srcs[j];
            g_ws[j+1]   = g_ws[j];
            j--;
        }
        g_ekey[j+1] = k;
        g_srcs[j+1] = s;
        g_ws[j+1]   = w;
    }
}

// ---------------- combined weight WcT[l][m][j] = sum_d ggc[l][j][d]*wih[m][d] --
__global__ void k_wc(const float* __restrict__ ggc, const float* __restrict__ wih) {
    __shared__ float wrow[HDIM];
    int lm = blockIdx.x;
    int l = lm / H3, m = lm % H3;
    int j = threadIdx.x;
    wrow[j] = wih[m*HDIM + j];
    __syncthreads();
    const float* grow = ggc + (size_t)(l*HDIM + j) * HDIM;
    float acc = 0.f;
    #pragma unroll 8
    for (int d = 0; d < HDIM; d++) acc += grow[d]*wrow[d];
    g_wc[(size_t)lm*HDIM + j] = acc;
}

// ---------------- h0 = emb[x] -----------------------------------------------
__global__ void k_embed(const int* __restrict__ x, const float* __restrict__ emb) {
    int i4 = blockIdx.x*256 + threadIdx.x;
    int n = i4 >> 6, c = i4 & 63;
    int v = x[n];
    ((float4*)g_h)[i4] = ((const float4*)emb)[(size_t)v*64 + c];
}

// ---------------- s = A h (CSR weighted aggregation), warp per node ----------
__global__ void k_agg() {
    int warp = (blockIdx.x*blockDim.x + threadIdx.x) >> 5;
    int lane = threadIdx.x & 31;
    if (warp >= NNODES) return;
    int s0 = g_rowptr[warp], s1 = g_rowptr[warp+1];
    float4 a0 = make_float4(0.f,0.f,0.f,0.f);
    float4 a1 = a0;
    for (int e = s0; e < s1; e++) {
        int   sp = g_srcs[e];
        float w  = g_ws[e];
        const float4* r = ((const float4*)g_h) + (size_t)sp*64;
        float4 v0 = r[lane], v1 = r[lane+32];
        a0.x += w*v0.x; a0.y += w*v0.y; a0.z += w*v0.z; a0.w += w*v0.w;
        a1.x += w*v1.x; a1.y += w*v1.y; a1.z += w*v1.z; a1.w += w*v1.w;
    }
    float4* o = ((float4*)g_s) + (size_t)warp*64;
    o[lane] = a0; o[lane+32] = a1;
}

// ---------------- GRU elementwise -------------------------------------------
__device__ __forceinline__ float gru1(float ir, float iz, float in_,
                                      float hr, float hz, float hn, float h) {
    float r  = 1.f / (1.f + expf(-(ir + hr)));
    float z  = 1.f / (1.f + expf(-(iz + hz)));
    float nn = tanhf(in_ + r*hn);
    return (1.f - z)*nn + z*h;
}
__global__ void k_gru() {
    int i4 = blockIdx.x*256 + threadIdx.x;
    int n = i4 >> 6, c = i4 & 63;
    const float4* gi = ((const float4*)g_gi) + (size_t)n*192;
    const float4* gh = ((const float4*)g_gh) + (size_t)n*192;
    float4 ir = gi[c], iz = gi[64 + c], inn = gi[128 + c];
    float4 hr = gh[c], hz = gh[64 + c], hn  = gh[128 + c];
    float4 h = ((float4*)g_h)[i4];
    h.x = gru1(ir.x, iz.x, inn.x, hr.x, hz.x, hn.x, h.x);
    h.y = gru1(ir.y, iz.y, inn.y, hr.y, hz.y, hn.y, h.y);
    h.z = gru1(ir.z, iz.z, inn.z, hr.z, hz.z, hn.z, h.z);
    h.w = gru1(ir.w, iz.w, inn.w, hr.w, hz.w, hn.w, h.w);
    ((float4*)g_h)[i4] = h;
}

// ---------------- gather + concat for output GEMM ----------------------------
__global__ void k_gcat(const int* __restrict__ gidx, const float* __restrict__ enc) {
    int i4 = blockIdx.x*256 + threadIdx.x;
    int r = i4 >> 7, c = i4 & 127;
    float4 v;
    if (c < 64) {
        int node = gidx[r];
        v = ((const float4*)g_h)[(size_t)node*64 + c];
    } else {
        v = ((const float4*)enc)[(size_t)r*64 + (c - 64)];
    }
    ((float4*)g_xcat)[i4] = v;
}

// ---------------- launch -----------------------------------------------------
extern "C" void kernel_launch(void* const* d_in, const int* in_sizes, int n_in,
                              void* d_out, int out_size) {
    const int*   x    = (const int*)d_in[0];
    const int*   ei   = (const int*)d_in[1];
    const float* ew   = (const float*)d_in[2];
    const int*   gidx = (const int*)d_in[3];
    const float* enc  = (const float*)d_in[5];
    const float* emb  = (const float*)d_in[6];
    const float* ggc  = (const float*)d_in[7];
    const float* wih  = (const float*)d_in[8];
    const float* whh  = (const float*)d_in[9];
    const float* bih  = (const float*)d_in[10];
    const float* bhh  = (const float*)d_in[11];
    const float* outw = (const float*)d_in[12];
    const float* outb = (const float*)d_in[13];
    float*       out  = (float*)d_out;

    (void)in_sizes; (void)n_in; (void)out_size;

    float *h_p, *s_p, *gi_p, *gh_p, *wc_p, *xcat_p;
    cudaGetSymbolAddress((void**)&h_p,    g_h);
    cudaGetSymbolAddress((void**)&s_p,    g_s);
    cudaGetSymbolAddress((void**)&gi_p,   g_gi);
    cudaGetSymbolAddress((void**)&gh_p,   g_gh);
    cudaGetSymbolAddress((void**)&wc_p,   g_wc);
    cudaGetSymbolAddress((void**)&xcat_p, g_xcat);

    cudaFuncSetAttribute(k_gemm_tc, cudaFuncAttributeMaxDynamicSharedMemorySize, TC_SMEM_BYTES);

    // CSR build (deterministic via k_sort)
    k_zero_fill<<<250, 256>>>();
    k_count    <<<4000, 256>>>(ei);
    k_scanA    <<<250, 256>>>();
    k_scanB    <<<1, 256>>>();
    k_scanC    <<<250, 256>>>();
    k_scatter  <<<4000, 256>>>(ei, ew);
    k_sort     <<<250, 256>>>();

    k_wc    <<<LGNN*H3, 256>>>(ggc, wih);
    k_embed <<<16000, 256>>>(x, emb);

    dim3 g1(H3/256, NNODES/128);   // (3, 500)
    for (int l = 0; l < LGNN; l++) {
        k_agg<<<8000, 256>>>();
        k_gemm_tc<<<g1, 512, TC_SMEM_BYTES>>>(s_p, wc_p + (size_t)l*H3*HDIM, bih, gi_p, HDIM, H3);
        k_gemm_tc<<<g1, 512, TC_SMEM_BYTES>>>(h_p, whh, bhh, gh_p, HDIM, H3);
        k_gru<<<16000, 256>>>();
    }

    k_gcat<<<4096, 256>>>(gidx, enc);
    dim3 g2(OUTD/256, NROWS_OUT/128);  // (1, 64)
    k_gemm_tc<<<g2, 512, TC_SMEM_BYTES>>>(xcat_p, outw, outb, out, 2*HDIM, OUTD);
}

// round 11
// speedup vs baseline: 1.6464x; 1.2330x over previous
#include <cuda_runtime.h>
#include <math.h>
#include <stdint.h>

#define NNODES 64000
#define HDIM   256
#define NEDGE  1024000
#define LGNN   4
#define BATCH  16
#define SEQL   512
#define OUTD   256
#define H3     768
#define NROWS_OUT (BATCH*SEQL)   // 8192

// Select tcgen05 path only on arch-/family-specific device passes (sm_103a etc).
#if !defined(__CUDA_ARCH__) || defined(__CUDA_ARCH_FEAT_SM103_ALL) || \
    defined(__CUDA_ARCH_FEAT_SM100_ALL) || defined(__CUDA_ARCH_FEAT_SM101_ALL) || \
    defined(__CUDA_ARCH_SPECIFIC__) || defined(__CUDA_ARCH_FAMILY_SPECIFIC__)
#define TC_PATH 1
#else
#define TC_PATH 0
#endif

// ---------------- scratch (device globals; no allocation allowed) -----------
__device__ float g_h  [NNODES*HDIM];
__device__ float g_s  [NNODES*HDIM];
__device__ float g_gi [NNODES*H3];
__device__ float g_gh [NNODES*H3];
__device__ float g_wc [LGNN*H3*HDIM];
__device__ int   g_rowptr[NNODES+1];
__device__ int   g_fill  [NNODES];
__device__ int   g_srcs  [NEDGE];
__device__ float g_ws    [NEDGE];
__device__ int   g_bsum  [256];
__device__ float g_xcat  [NROWS_OUT*2*HDIM];

#if TC_PATH
// ================= tcgen05 helpers ==========================================
__device__ __forceinline__ uint32_t smem_u32(const void* p) {
    uint32_t a;
    asm("{ .reg .u64 t; cvta.to.shared.u64 t, %1; cvt.u32.u64 %0, t; }" : "=r"(a) : "l"(p));
    return a;
}
__device__ __forceinline__ uint32_t elect_one() {
    uint32_t pred;
    asm volatile("{\n\t.reg .pred p;\n\telect.sync _|p, 0xFFFFFFFF;\n\tselp.b32 %0, 1, 0, p;\n\t}" : "=r"(pred));
    return pred;
}
#define MBAR_INIT(a, c) asm volatile("mbarrier.init.shared.b64 [%0], %1;" :: "r"(a), "r"(c) : "memory")
#define MBAR_INVAL(a)   asm volatile("mbarrier.inval.shared.b64 [%0];" :: "r"(a) : "memory")
#define MBAR_WAIT(a, ph) do {                                                   \
    uint32_t _m = (a), _p = (ph), _d;                                           \
    asm volatile("{\n\t.reg .pred p;\n\t"                                       \
        "mbarrier.try_wait.parity.acquire.cta.shared::cta.b64 p, [%1], %2;\n\t" \
        "selp.b32 %0, 1, 0, p;\n\t}" : "=r"(_d) : "r"(_m), "r"(_p) : "memory"); \
    if (!_d) {                                                                  \
        asm volatile("{\n\t.reg .pred P1;\n\t"                                  \
            "W_%=:\n\t"                                                         \
            "mbarrier.try_wait.parity.acquire.cta.shared::cta.b64 P1, [%0], %1, 0x989680;\n\t" \
            "@P1 bra.uni D_%=;\n\t"                                             \
            "bra.uni W_%=;\n\t"                                                 \
            "D_%=:\n\t}" :: "r"(_m), "r"(_p) : "memory");                       \
    }                                                                           \
} while (0)
#define TC_ALLOC(sa, n)   asm volatile("tcgen05.alloc.cta_group::1.sync.aligned.shared::cta.b32 [%0], %1;" :: "r"(sa), "r"(n) : "memory")
#define TC_DEALLOC(t, n)  asm volatile("tcgen05.dealloc.cta_group::1.sync.aligned.b32 %0, %1;" :: "r"(t), "r"(n))
#define TC_RELINQ()       asm volatile("tcgen05.relinquish_alloc_permit.cta_group::1.sync.aligned;")
#define TC_COMMIT(mb)     asm volatile("tcgen05.commit.cta_group::1.mbarrier::arrive::one.shared::cluster.b64 [%0];" :: "r"(mb) : "memory")
#define TC_FENCE_AFTER()  asm volatile("tcgen05.fence::after_thread_sync;" ::: "memory")
#define TC_WAIT_LD()      asm volatile("tcgen05.wait::ld.sync.aligned;" ::: "memory")
#define FENCE_ASYNC()     asm volatile("fence.proxy.async.shared::cta;" ::: "memory")

#define TC_LD_X32(r, ta) \
    asm volatile("tcgen05.ld.sync.aligned.32x32b.x32.b32 " \
        "{%0, %1, %2, %3, %4, %5, %6, %7, %8, %9, %10, %11, %12, %13, %14, %15, " \
        " %16, %17, %18, %19, %20, %21, %22, %23, %24, %25, %26, %27, %28, %29, %30, %31}, [%32];" \
        : "=r"((r)[0]),  "=r"((r)[1]),  "=r"((r)[2]),  "=r"((r)[3]), \
          "=r"((r)[4]),  "=r"((r)[5]),  "=r"((r)[6]),  "=r"((r)[7]), \
          "=r"((r)[8]),  "=r"((r)[9]),  "=r"((r)[10]), "=r"((r)[11]), \
          "=r"((r)[12]), "=r"((r)[13]), "=r"((r)[14]), "=r"((r)[15]), \
          "=r"((r)[16]), "=r"((r)[17]), "=r"((r)[18]), "=r"((r)[19]), \
          "=r"((r)[20]), "=r"((r)[21]), "=r"((r)[22]), "=r"((r)[23]), \
          "=r"((r)[24]), "=r"((r)[25]), "=r"((r)[26]), "=r"((r)[27]), \
          "=r"((r)[28]), "=r"((r)[29]), "=r"((r)[30]), "=r"((r)[31]) \
        : "r"(ta))

static constexpr uint64_t DESC_BASE_SW128 =
    (uint64_t(2)  << 61) | (uint64_t(1) << 46) | (uint64_t(64) << 32) | (uint64_t(1) << 16);
__device__ __forceinline__ uint64_t make_desc(uint32_t addr) {
    return DESC_BASE_SW128 | ((uint64_t)(addr >> 4) & 0x3FFF);
}
__device__ __forceinline__ uint32_t tf32cvt(float f) {
    uint32_t r;
    asm("cvt.rna.tf32.f32 %0, %1;" : "=r"(r) : "f"(f));
    return r;
}
__device__ __forceinline__ void mma_tf32(uint32_t d_tmem, uint64_t a_desc, uint64_t b_desc,
                                         uint32_t idesc, uint32_t en) {
    asm volatile("{\n\t.reg .pred p;\n\tsetp.ne.u32 p, %4, 0;\n\t"
        "tcgen05.mma.cta_group::1.kind::tf32 [%0], %1, %2, %3, {%5, %5, %5, %5}, p;\n\t}"
        :: "r"(d_tmem), "l"(a_desc), "l"(b_desc), "r"(idesc), "r"(en), "r"(0u) : "memory");
}

// idesc: dtype F32(1<<4), atype/btype TF32, M=128 (8<<24), N=128 (16<<17)
static constexpr uint32_t IDESC_N128 = (8u << 24) | (16u << 17) | (2u << 10) | (2u << 7) | (1u << 4);

// fill a 128-row x 32-float chunk (one SW128 atom column), tf32-rounded
__device__ __forceinline__ void fill_chunk32(char* smem, int dst, const float* __restrict__ src,
                                             int rowBase, int K, int k0, int tid) {
    #pragma unroll
    for (int it = 0; it < 4; it++) {
        int idx = it*256 + tid;           // 1024 float4 total
        int row = idx >> 3, c4 = (idx & 7) * 4;
        float4 v = *(const float4*)(src + (size_t)(rowBase + row)*K + k0 + c4);
        uint4 t;
        t.x = tf32cvt(v.x); t.y = tf32cvt(v.y); t.z = tf32cvt(v.z); t.w = tf32cvt(v.w);
        int aoff = (row >> 3)*1024 + (row & 7)*128 + c4*4;
        aoff ^= ((aoff >> 3) & 0x70);
        *(uint4*)(smem + dst + aoff) = t;
    }
}
#endif  // TC_PATH helpers

// SMEM plan: [0] tmem ptr | [8] mbar | [16..528) bias | [2048..) 2 x 32KB buffers
// (A 16KB + B 16KB per chunk buffer). Total 67.5 KB -> 3 CTAs/SM.
#define GBUF0   2048
#define GBUFSZ  32768
#define TC_SMEM_BYTES (2048 + 2*32768)

// C[n, m] = sum_k A[n,k]*B[m,k] + bias[m]; block tile 128x128, K chunks of 32
__global__ void __launch_bounds__(256, 3) k_gemm_tc(const float* __restrict__ A,
                                                    const float* __restrict__ B,
                                                    const float* __restrict__ bias,
                                                    float* __restrict__ C, int K, int M) {
#if TC_PATH
    extern __shared__ char smc[];
    uint32_t sb = smem_u32(smc);
    int tid = threadIdx.x;
    int wid = tid >> 5, lid = tid & 31;
    int rowBase = blockIdx.y * 128;
    int colBase = blockIdx.x * 128;

    if (wid == 0) { TC_ALLOC(sb, 128); TC_RELINQ(); }
    if (tid == 0) MBAR_INIT(sb + 8, 1);
    if (tid < 128) *(float*)(smc + 16 + tid*4) = bias[colBase + tid];

    // prologue: chunk 0
    fill_chunk32(smc, GBUF0,         A, rowBase, K, 0, tid);
    fill_chunk32(smc, GBUF0 + 16384, B, colBase, K, 0, tid);
    __syncthreads();

    uint32_t tmem;
    asm volatile("ld.shared.b32 %0, [%1];" : "=r"(tmem) : "r"(sb));

    int nch = K / 32;
    for (int c = 0; c < nch; c++) {
        int cur = c & 1;
        uint32_t aA = sb + GBUF0 + cur*GBUFSZ;
        uint32_t aB = aA + 16384;
        if (wid == 0) {
            FENCE_ASYNC();
            if (elect_one()) {
                uint64_t ad = make_desc(aA), bd = make_desc(aB);
                #pragma unroll
                for (int s = 0; s < 4; s++) {
                    mma_tf32(tmem, ad + s*2, bd + s*2, IDESC_N128, (c | s) != 0);
                }
                TC_COMMIT(sb + 8);
            }
        }
        if (c + 1 < nch) {
            int nxt = cur ^ 1;
            fill_chunk32(smc, GBUF0 + nxt*GBUFSZ,         A, rowBase, K, (c+1)*32, tid);
            fill_chunk32(smc, GBUF0 + nxt*GBUFSZ + 16384, B, colBase, K, (c+1)*32, tid);
        }
        MBAR_WAIT(sb + 8, c & 1);
        __syncthreads();
    }

    // epilogue: TMEM -> staged SMEM -> coalesced global
    TC_FENCE_AFTER();
    float* stage = (float*)(smc + GBUF0);          // 128 rows x 36 floats (18 KB)
    const float* bs = (const float*)(smc + 16);
    for (int g = 0; g < 4; g++) {
        if (wid < 4) {
            uint32_t d[32];
            TC_LD_X32(d, tmem + g*32);
            TC_WAIT_LD();
            int rl = wid*32 + lid;
            #pragma unroll
            for (int j = 0; j < 32; j++)
                stage[rl*36 + j] = __uint_as_float(d[j]) + bs[g*32 + j];
        }
        __syncthreads();
        #pragma unroll
        for (int it = 0; it < 4; it++) {
            int idx = it*256 + tid;               // 1024 float4
            int r = idx >> 3, c8 = idx & 7;
            float4 v = *(float4*)(stage + r*36 + c8*4);
            *(float4*)(C + (size_t)(rowBase + r)*M + colBase + g*32 + c8*4) = v;
        }
        __syncthreads();
    }

    if (tid == 0) MBAR_INVAL(sb + 8);
    __syncthreads();
    if (wid == 0) TC_DEALLOC(tmem, 128);
#else
    // ---- fp32 fallback (non arch-specific target): 128x128 tile, 8x8/thread ----
    extern __shared__ char smc[];
    float* As = (float*)(smc + 1024);             // [16][132]
    float* Bs = As + 16*132;                      // [16][132]
    int tid = threadIdx.x;
    int ty = tid >> 4, tx = tid & 15;
    int rowBase = blockIdx.y * 128;
    int colBase = blockIdx.x * 128;

    float acc[8][8];
    #pragma unroll
    for (int i = 0; i < 8; i++)
        #pragma unroll
        for (int j = 0; j < 8; j++) acc[i][j] = 0.f;

    for (int k0 = 0; k0 < K; k0 += 16) {
        #pragma unroll
        for (int q = 0; q < 2; q++) {
            int f = tid + q*256;
            int r = f >> 2, kc = (f & 3) * 4;
            float4 va = *(const float4*)(A + (size_t)(rowBase + r)*K + k0 + kc);
            As[(kc+0)*132 + r] = va.x; As[(kc+1)*132 + r] = va.y;
            As[(kc+2)*132 + r] = va.z; As[(kc+3)*132 + r] = va.w;
            float4 vb = *(const float4*)(B + (size_t)(colBase + r)*K + k0 + kc);
            Bs[(kc+0)*132 + r] = vb.x; Bs[(kc+1)*132 + r] = vb.y;
            Bs[(kc+2)*132 + r] = vb.z; Bs[(kc+3)*132 + r] = vb.w;
        }
        __syncthreads();
        #pragma unroll
        for (int kk = 0; kk < 16; kk++) {
            float a[8], b[8];
            #pragma unroll
            for (int i = 0; i < 8; i++) a[i] = As[kk*132 + ty*8 + i];
            #pragma unroll
            for (int j = 0; j < 8; j++) b[j] = Bs[kk*132 + tx*8 + j];
            #pragma unroll
            for (int i = 0; i < 8; i++)
                #pragma unroll
                for (int j = 0; j < 8; j++) acc[i][j] += a[i]*b[j];
        }
        __syncthreads();
    }
    #pragma unroll
    for (int i = 0; i < 8; i++) {
        #pragma unroll
        for (int j = 0; j < 8; j += 4) {
            float4 o;
            o.x = acc[i][j+0] + bias[colBase + tx*8 + j+0];
            o.y = acc[i][j+1] + bias[colBase + tx*8 + j+1];
            o.z = acc[i][j+2] + bias[colBase + tx*8 + j+2];
            o.w = acc[i][j+3] + bias[colBase + tx*8 + j+3];
            *(float4*)(C + (size_t)(rowBase + ty*8 + i)*M + colBase + tx*8 + j) = o;
        }
    }
#endif
}

// ---------------- CSR build --------------------------------------------------
__global__ void k_zero_fill() {
    int i = blockIdx.x*256 + threadIdx.x;
    if (i < NNODES) g_fill[i] = 0;
}
__global__ void k_count(const int* __restrict__ ei) {
    int e = blockIdx.x*256 + threadIdx.x;
    if (e < NEDGE) atomicAdd(&g_fill[ei[NEDGE + e]], 1);
}
__global__ void k_scanA() {
    __shared__ int sh[256];
    int t = threadIdx.x;
    int i = blockIdx.x*256 + t;
    int v = g_fill[i];
    sh[t] = v; __syncthreads();
    #pragma unroll
    for (int off = 1; off < 256; off <<= 1) {
        int x = (t >= off) ? sh[t-off] : 0;
        __syncthreads();
        sh[t] += x;
        __syncthreads();
    }
    g_rowptr[i] = sh[t] - v;
    if (t == 255) g_bsum[blockIdx.x] = sh[t];
}
__global__ void k_scanB() {
    __shared__ int sh[256];
    int t = threadIdx.x;
    int v = (t < 250) ? g_bsum[t] : 0;
    sh[t] = v; __syncthreads();
    #pragma unroll
    for (int off = 1; off < 256; off <<= 1) {
        int x = (t >= off) ? sh[t-off] : 0;
        __syncthreads();
        sh[t] += x;
        __syncthreads();
    }
    if (t < 250) g_bsum[t] = sh[t] - v;
}
__global__ void k_scanC() {
    int t = threadIdx.x;
    int i = blockIdx.x*256 + t;
    g_rowptr[i] += g_bsum[blockIdx.x];
    g_fill[i] = 0;
    if (i == 0) g_rowptr[NNODES] = NEDGE;
}
__global__ void k_scatter(const int* __restrict__ ei, const float* __restrict__ ew) {
    int e = blockIdx.x*256 + threadIdx.x;
    if (e >= NEDGE) return;
    int d = ei[NEDGE + e];
    int p = g_rowptr[d] + atomicAdd(&g_fill[d], 1);
    g_srcs[p] = ei[e];
    g_ws[p]   = ew[e];
}

// ---------------- combined weight WcT[l][m][j] = sum_d ggc[l][j][d]*wih[m][d] --
__global__ void k_wc(const float* __restrict__ ggc, const float* __restrict__ wih) {
    __shared__ float wrow[HDIM];
    int lm = blockIdx.x;
    int l = lm / H3, m = lm % H3;
    int j = threadIdx.x;
    wrow[j] = wih[m*HDIM + j];
    __syncthreads();
    const float* grow = ggc + (size_t)(l*HDIM + j) * HDIM;
    float acc = 0.f;
    #pragma unroll 8
    for (int d = 0; d < HDIM; d++) acc += grow[d]*wrow[d];
    g_wc[(size_t)lm*HDIM + j] = acc;
}

// ---------------- h0 = emb[x] -----------------------------------------------
__global__ void k_embed(const int* __restrict__ x, const float* __restrict__ emb) {
    int i4 = blockIdx.x*256 + threadIdx.x;
    int n = i4 >> 6, c = i4 & 63;
    int v = x[n];
    ((float4*)g_h)[i4] = ((const float4*)emb)[(size_t)v*64 + c];
}

// ---------------- s = A h (CSR weighted aggregation), warp per node ----------
__global__ void k_agg() {
    int warp = (blockIdx.x*blockDim.x + threadIdx.x) >> 5;
    int lane = threadIdx.x & 31;
    if (warp >= NNODES) return;
    int s0 = g_rowptr[warp], s1 = g_rowptr[warp+1];
    float4 a0 = make_float4(0.f,0.f,0.f,0.f);
    float4 a1 = a0;
    for (int e = s0; e < s1; e++) {
        int   sp = g_srcs[e];
        float w  = g_ws[e];
        const float4* r = ((const float4*)g_h) + (size_t)sp*64;
        float4 v0 = r[lane], v1 = r[lane+32];
        a0.x += w*v0.x; a0.y += w*v0.y; a0.z += w*v0.z; a0.w += w*v0.w;
        a1.x += w*v1.x; a1.y += w*v1.y; a1.z += w*v1.z; a1.w += w*v1.w;
    }
    float4* o = ((float4*)g_s) + (size_t)warp*64;
    o[lane] = a0; o[lane+32] = a1;
}

// ---------------- GRU elementwise -------------------------------------------
__device__ __forceinline__ float gru1(float ir, float iz, float in_,
                                      float hr, float hz, float hn, float h) {
    float r  = 1.f / (1.f + expf(-(ir + hr)));
    float z  = 1.f / (1.f + expf(-(iz + hz)));
    float nn = tanhf(in_ + r*hn);
    return (1.f - z)*nn + z*h;
}
__global__ void k_gru() {
    int i4 = blockIdx.x*256 + threadIdx.x;
    int n = i4 >> 6, c = i4 & 63;
    const float4* gi = ((const float4*)g_gi) + (size_t)n*192;
    const float4* gh = ((const float4*)g_gh) + (size_t)n*192;
    float4 ir = gi[c], iz = gi[64 + c], inn = gi[128 + c];
    float4 hr = gh[c], hz = gh[64 + c], hn  = gh[128 + c];
    float4 h = ((float4*)g_h)[i4];
    h.x = gru1(ir.x, iz.x, inn.x, hr.x, hz.x, hn.x, h.x);
    h.y = gru1(ir.y, iz.y, inn.y, hr.y, hz.y, hn.y, h.y);
    h.z = gru1(ir.z, iz.z, inn.z, hr.z, hz.z, hn.z, h.z);
    h.w = gru1(ir.w, iz.w, inn.w, hr.w, hz.w, hn.w, h.w);
    ((float4*)g_h)[i4] = h;
}

// ---------------- gather + concat for output GEMM ----------------------------
__global__ void k_gcat(const int* __restrict__ gidx, const float* __restrict__ enc) {
    int i4 = blockIdx.x*256 + threadIdx.x;
    int r = i4 >> 7, c = i4 & 127;
    float4 v;
    if (c < 64) {
        int node = gidx[r];
        v = ((const float4*)g_h)[(size_t)node*64 + c];
    } else {
        v = ((const float4*)enc)[(size_t)r*64 + (c - 64)];
    }
    ((float4*)g_xcat)[i4] = v;
}

// ---------------- launch -----------------------------------------------------
extern "C" void kernel_launch(void* const* d_in, const int* in_sizes, int n_in,
                              void* d_out, int out_size) {
    const int*   x    = (const int*)d_in[0];
    const int*   ei   = (const int*)d_in[1];
    const float* ew   = (const float*)d_in[2];
    const int*   gidx = (const int*)d_in[3];
    const float* enc  = (const float*)d_in[5];
    const float* emb  = (const float*)d_in[6];
    const float* ggc  = (const float*)d_in[7];
    const float* wih  = (const float*)d_in[8];
    const float* whh  = (const float*)d_in[9];
    const float* bih  = (const float*)d_in[10];
    const float* bhh  = (const float*)d_in[11];
    const float* outw = (const float*)d_in[12];
    const float* outb = (const float*)d_in[13];
    float*       out  = (float*)d_out;

    (void)in_sizes; (void)n_in; (void)out_size;

    float *h_p, *s_p, *gi_p, *gh_p, *wc_p, *xcat_p;
    cudaGetSymbolAddress((void**)&h_p,    g_h);
    cudaGetSymbolAddress((void**)&s_p,    g_s);
    cudaGetSymbolAddress((void**)&gi_p,   g_gi);
    cudaGetSymbolAddress((void**)&gh_p,   g_gh);
    cudaGetSymbolAddress((void**)&wc_p,   g_wc);
    cudaGetSymbolAddress((void**)&xcat_p, g_xcat);

    cudaFuncSetAttribute(k_gemm_tc, cudaFuncAttributeMaxDynamicSharedMemorySize, TC_SMEM_BYTES);

    // CSR build (atomic bucket order; tolerance-checked output, sort unnecessary)
    k_zero_fill<<<250, 256>>>();
    k_count    <<<4000, 256>>>(ei);
    k_scanA    <<<250, 256>>>();
    k_scanB    <<<1, 256>>>();
    k_scanC    <<<250, 256>>>();
    k_scatter  <<<4000, 256>>>(ei, ew);

    k_wc    <<<LGNN*H3, 256>>>(ggc, wih);
    k_embed <<<16000, 256>>>(x, emb);

    dim3 g1(H3/128, NNODES/128);   // (6, 500)
    for (int l = 0; l < LGNN; l++) {
        k_agg<<<8000, 256>>>();
        k_gemm_tc<<<g1, 256, TC_SMEM_BYTES>>>(s_p, wc_p + (size_t)l*H3*HDIM, bih, gi_p, HDIM, H3);
        k_gemm_tc<<<g1, 256, TC_SMEM_BYTES>>>(h_p, whh, bhh, gh_p, HDIM, H3);
        k_gru<<<16000, 256>>>();
    }

    k_gcat<<<4096, 256>>>(gidx, enc);
    dim3 g2(OUTD/128, NROWS_OUT/128);  // (2, 64)
    k_gemm_tc<<<g2, 256, TC_SMEM_BYTES>>>(xcat_p, outw, outb, out, 2*HDIM, OUTD);
}